// round 14
// baseline (speedup 1.0000x reference)
#include <cuda_runtime.h>

#define SS   21      // search size
#define PAD  10
#define BS   4       // block size
#define TILE 24      // rows: BS + SS - 1
#define TC   28      // tile cols: 2*BS + SS - 1 (pitch)
#define H    256
#define W    256

__global__ __launch_bounds__(96, 16)
void pred_kernel(const float* __restrict__ im1,
                 const float* __restrict__ im2,
                 float* __restrict__ out)
{
    __shared__ __align__(16) float im2t[TILE * TC];   // 24 x 28
    __shared__ __align__(16) float im1t[32];          // 4 rows x 8 cols (both subs)
    __shared__ __align__(16) float red[2][21][16];    // [sub][i][pixel] weighted sums
    __shared__ __align__(8)  float smsg[2][21][2];    // [sub][i][{min,lsum}]

    const int t  = threadIdx.x;
    const int bx = blockIdx.x, by = blockIdx.y, b = blockIdx.z;
    const float* i1 = im1 + b * H * W;
    const float* i2 = im2 + b * H * W;

    const int x0 = bx * (2 * BS) - PAD;   // even
    const int y0 = by * BS - PAD;

    // ---- Phase 0: load 24x28 im2 halo tile (shared by both sub-blocks) ----
    if (bx >= 2 && bx <= 29 && by >= 3 && by <= 60) {
        // interior: coalesced float2 (x0 even). 336 float2 over 96 threads:
        // 3 full passes + 48-thread remainder (peeled, no per-iter bounds test).
        #pragma unroll
        for (int p = 0; p < 3; p++) {
            int idx = t + p * 96;
            int r  = idx / (TC / 2);
            int c2 = idx - r * (TC / 2);
            float2 v = *(const float2*)(i2 + (y0 + r) * W + x0 + c2 * 2);
            *(float2*)&im2t[r * TC + c2 * 2] = v;
        }
        if (t < 48) {
            int idx = t + 288;
            int r  = idx / (TC / 2);
            int c2 = idx - r * (TC / 2);
            float2 v = *(const float2*)(i2 + (y0 + r) * W + x0 + c2 * 2);
            *(float2*)&im2t[r * TC + c2 * 2] = v;
        }
    } else {
        // border: predicated zero-pad
        #pragma unroll
        for (int q = 0; q < 7; q++) {
            int idx = t + q * 96;
            if (idx < TILE * TC) {
                int r = idx / TC, c = idx - r * TC;
                int y = y0 + r, x = x0 + c;
                float v = 0.0f;
                if ((unsigned)y < (unsigned)H && (unsigned)x < (unsigned)W)
                    v = i2[y * W + x];
                im2t[r * TC + c] = v;
            }
        }
    }
    if (t < 8) {
        // im1 4x8 block (both sub-blocks), 16B-aligned vector loads
        int r = t >> 1, q = t & 1;
        float4 v = *(const float4*)(i1 + (by * BS + r) * W + bx * (2 * BS) + q * 4);
        *(float4*)&im1t[r * 8 + q * 4] = v;
    }
    __syncthreads();

    // ---- mapping: s = sub-block (t/48), u = t%48, i = u>>1, h = u&1 ----
    const int s  = t / 48;
    const int u  = t - s * 48;
    const int i  = u >> 1;            // shift row 0..20
    const int h  = u & 1;             // row-pair selector
    const bool act = (u < 42);
    const int lane = t & 31;
    const unsigned pmask = 3u << (lane & ~1);   // shuffle pair mask

    const unsigned sbA = (unsigned)__cvta_generic_to_shared(
                             &im2t[(2 * h + i) * TC + s * BS]);
    const unsigned sbB = sbA + TC * 4u;   // next row
    const unsigned ib  = (unsigned)__cvta_generic_to_shared(
                             &im1t[2 * h * 8 + s * BS]);

    float vol[SS];
    float lmin = 1e30f;

    // ---- Phase 1: 2-row SADs with sliding-window loads, pair-reduce, local min
    if (act) {
        float a0, a1, a2, a3, b0, b1, b2, b3;
        asm("ld.shared.v4.f32 {%0,%1,%2,%3}, [%4];"
            : "=f"(a0), "=f"(a1), "=f"(a2), "=f"(a3) : "r"(ib));
        asm("ld.shared.v4.f32 {%0,%1,%2,%3}, [%4];"
            : "=f"(b0), "=f"(b1), "=f"(b2), "=f"(b3) : "r"(ib + 32u));
        float rA[TILE], rB[TILE];
        #pragma unroll
        for (int g = 0; g < 6; g++) {
            asm("ld.shared.v4.f32 {%0,%1,%2,%3}, [%4];"
                : "=f"(rA[4*g]), "=f"(rA[4*g+1]), "=f"(rA[4*g+2]), "=f"(rA[4*g+3])
                : "r"(sbA + 16u * g));
            asm("ld.shared.v4.f32 {%0,%1,%2,%3}, [%4];"
                : "=f"(rB[4*g]), "=f"(rB[4*g+1]), "=f"(rB[4*g+2]), "=f"(rB[4*g+3])
                : "r"(sbB + 16u * g));
            if (g >= 1) {
                #pragma unroll
                for (int jj = 0; jj < 4; jj++) {
                    int j = 4 * (g - 1) + jj;
                    vol[j] = fabsf(a0 - rA[j])     + fabsf(a1 - rA[j + 1])
                           + fabsf(a2 - rA[j + 2]) + fabsf(a3 - rA[j + 3])
                           + fabsf(b0 - rB[j])     + fabsf(b1 - rB[j + 1])
                           + fabsf(b2 - rB[j + 2]) + fabsf(b3 - rB[j + 3]);
                }
            }
        }
        vol[20] = fabsf(a0 - rA[20]) + fabsf(a1 - rA[21])
                + fabsf(a2 - rA[22]) + fabsf(a3 - rA[23])
                + fabsf(b0 - rB[20]) + fabsf(b1 - rB[21])
                + fabsf(b2 - rB[22]) + fabsf(b3 - rB[23]);

        // single-step pair allreduce over h (pair lanes end identical)
        #pragma unroll
        for (int j = 0; j < SS; j++)
            vol[j] += __shfl_xor_sync(pmask, vol[j], 1);

        // lane-local min — no CTA-wide reduction needed
        lmin = vol[0];
        #pragma unroll
        for (int j = 1; j < SS; j++) lmin = fminf(lmin, vol[j]);
        if (h == 0) smsg[s][i][0] = lmin;    // for phase-4 rescale
    }

    // ---- Phase 3: fused weights (local offset) + 2-row accumulation ----
    if (act) {
        // w = 2^(K*vol + M), K = -6.25*log2(e), M = -K*lmin (lane-local)
        const float K = -9.016844005555897f;
        const float M = -K * lmin;
        float lsum = 0.0f;
        float c0 = 0.f, c1 = 0.f, c2 = 0.f, c3 = 0.f;   // pixel row 2h
        float d0 = 0.f, d1 = 0.f, d2 = 0.f, d3 = 0.f;   // pixel row 2h+1
        float rA[TILE], rB[TILE];
        #pragma unroll
        for (int g = 0; g < 6; g++) {
            asm volatile("ld.shared.v4.f32 {%0,%1,%2,%3}, [%4];"
                : "=f"(rA[4*g]), "=f"(rA[4*g+1]), "=f"(rA[4*g+2]), "=f"(rA[4*g+3])
                : "r"(sbA + 16u * g));
            asm volatile("ld.shared.v4.f32 {%0,%1,%2,%3}, [%4];"
                : "=f"(rB[4*g]), "=f"(rB[4*g+1]), "=f"(rB[4*g+2]), "=f"(rB[4*g+3])
                : "r"(sbB + 16u * g));
            if (g >= 1) {
                #pragma unroll
                for (int jj = 0; jj < 4; jj++) {
                    int j = 4 * (g - 1) + jj;
                    float e = fmaf(vol[j], K, M);
                    float wv;
                    asm("ex2.approx.ftz.f32 %0, %1;" : "=f"(wv) : "f"(e));
                    lsum += wv;
                    c0 = fmaf(wv, rA[j],     c0);
                    c1 = fmaf(wv, rA[j + 1], c1);
                    c2 = fmaf(wv, rA[j + 2], c2);
                    c3 = fmaf(wv, rA[j + 3], c3);
                    d0 = fmaf(wv, rB[j],     d0);
                    d1 = fmaf(wv, rB[j + 1], d1);
                    d2 = fmaf(wv, rB[j + 2], d2);
                    d3 = fmaf(wv, rB[j + 3], d3);
                }
            }
        }
        {
            float e = fmaf(vol[20], K, M);
            float wv;
            asm("ex2.approx.ftz.f32 %0, %1;" : "=f"(wv) : "f"(e));
            lsum += wv;
            c0 = fmaf(wv, rA[20], c0); c1 = fmaf(wv, rA[21], c1);
            c2 = fmaf(wv, rA[22], c2); c3 = fmaf(wv, rA[23], c3);
            d0 = fmaf(wv, rB[20], d0); d1 = fmaf(wv, rB[21], d1);
            d2 = fmaf(wv, rB[22], d2); d3 = fmaf(wv, rB[23], d3);
        }
        if (h == 0) smsg[s][i][1] = lsum;    // pair lanes hold identical lsum
        // contiguous vector stores: [pixel rows 2h (c) and 2h+1 (d)]
        *(float4*)&red[s][i][8 * h]     = make_float4(c0, c1, c2, c3);
        *(float4*)&red[s][i][8 * h + 4] = make_float4(d0, d1, d2, d3);
    }
    __syncthreads();

    // ---- Phase 4: split rescale-merge over 21 shift-rows (64 threads) ----
    // warp so handles sub-block so; half-warps split the q range (0..10 / 11..20).
    if (t < 64) {
        const int so   = t >> 5;
        const int half = (t >> 4) & 1;
        const int tt   = t & 15;
        const float K  = -9.016844005555897f;

        // local min over own half (compile-time trip counts)
        float mh;
        if (half == 0) {
            mh = smsg[so][0][0];
            #pragma unroll
            for (int q = 1; q < 11; q++) mh = fminf(mh, smsg[so][q][0]);
        } else {
            mh = smsg[so][11][0];
            #pragma unroll
            for (int q = 12; q < 21; q++) mh = fminf(mh, smsg[so][q][0]);
        }
        // converged: global offset via cross-half shuffle
        float mstar = fminf(mh, __shfl_xor_sync(0xffffffffu, mh, 16));

        float sum = 0.0f, ws = 0.0f;
        if (half == 0) {
            #pragma unroll
            for (int q = 0; q < 11; q++) {
                float2 msv = *(const float2*)&smsg[so][q][0];
                float e = K * (msv.x - mstar);   // <= 0
                float sc;
                asm("ex2.approx.ftz.f32 %0, %1;" : "=f"(sc) : "f"(e));
                sum = fmaf(sc, red[so][q][tt], sum);
                ws  = fmaf(sc, msv.y,          ws);
            }
        } else {
            #pragma unroll
            for (int q = 11; q < 21; q++) {
                float2 msv = *(const float2*)&smsg[so][q][0];
                float e = K * (msv.x - mstar);   // <= 0
                float sc;
                asm("ex2.approx.ftz.f32 %0, %1;" : "=f"(sc) : "f"(e));
                sum = fmaf(sc, red[so][q][tt], sum);
                ws  = fmaf(sc, msv.y,          ws);
            }
        }
        // converged: combine halves
        sum += __shfl_xor_sync(0xffffffffu, sum, 16);
        ws  += __shfl_xor_sync(0xffffffffu, ws, 16);

        if (half == 0) {
            int py2 = tt >> 2, px2 = tt & 3;
            out[b * H * W + (by * BS + py2) * W + bx * (2 * BS) + so * BS + px2]
                = __fdividef(sum, ws);
        }
    }
}

extern "C" void kernel_launch(void* const* d_in, const int* in_sizes, int n_in,
                              void* d_out, int out_size) {
    const float* im1 = (const float*)d_in[0];
    const float* im2 = (const float*)d_in[1];
    float* out = (float*)d_out;
    dim3 grid(W / (2 * BS), H / BS, 2);   // (32, 64, 2)
    pred_kernel<<<grid, 96>>>(im1, im2, out);
}

// round 15
// speedup vs baseline: 1.0285x; 1.0285x over previous
#include <cuda_runtime.h>

#define SS   21      // search size
#define PAD  10
#define BS   4       // block size
#define NB   4       // sub-blocks per CTA (horizontal)
#define TILE 24      // rows: BS + SS - 1
#define TC   36      // tile cols: NB*BS + SS - 1 (pitch, 144B: 16B-aligned)
#define NT   192
#define H    256
#define W    256

__global__ __launch_bounds__(NT, 8)
void pred_kernel(const float* __restrict__ im1,
                 const float* __restrict__ im2,
                 float* __restrict__ out)
{
    __shared__ __align__(16) float im2t[TILE * TC];   // 24 x 36
    __shared__ __align__(16) float im1t[4 * 16];      // 4 rows x 16 cols (4 subs)
    __shared__ __align__(16) float red[NB][21][16];   // [sub][i][pixel]
    __shared__ __align__(8)  float smsg[NB][21][2];   // [sub][i][{min,lsum}]

    const int t  = threadIdx.x;
    const int bx = blockIdx.x, by = blockIdx.y, b = blockIdx.z;
    const float* i1 = im1 + b * H * W;
    const float* i2 = im2 + b * H * W;

    const int x0 = bx * (NB * BS) - PAD;   // even
    const int y0 = by * BS - PAD;

    // ---- Phase 0: load 24x36 im2 halo tile (shared by 4 sub-blocks) ----
    if (bx >= 1 && bx <= 14 && by >= 3 && by <= 60) {
        // interior: coalesced float2 (x0 even). 432 float2 over 192 threads.
        #pragma unroll
        for (int p = 0; p < 3; p++) {
            int idx = t + p * NT;
            if (idx < TILE * (TC / 2)) {
                int r  = idx / (TC / 2);
                int c2 = idx - r * (TC / 2);
                float2 v = *(const float2*)(i2 + (y0 + r) * W + x0 + c2 * 2);
                *(float2*)&im2t[r * TC + c2 * 2] = v;
            }
        }
    } else {
        // border: predicated zero-pad
        #pragma unroll
        for (int q = 0; q < 5; q++) {
            int idx = t + q * NT;
            if (idx < TILE * TC) {
                int r = idx / TC, c = idx - r * TC;
                int y = y0 + r, x = x0 + c;
                float v = 0.0f;
                if ((unsigned)y < (unsigned)H && (unsigned)x < (unsigned)W)
                    v = i2[y * W + x];
                im2t[r * TC + c] = v;
            }
        }
    }
    if (t < 16) {
        // im1 4x16 block (all 4 sub-blocks), 16B-aligned vector loads
        int r = t >> 2, q = t & 3;
        float4 v = *(const float4*)(i1 + (by * BS + r) * W + bx * (NB * BS) + q * 4);
        *(float4*)&im1t[r * 16 + q * 4] = v;
    }
    __syncthreads();

    // ---- mapping: s = sub-block (t/48), u = t%48, i = u>>1, h = u&1 ----
    const int s  = t / 48;
    const int u  = t - s * 48;
    const int i  = u >> 1;            // shift row 0..20
    const int h  = u & 1;             // row-pair selector
    const bool act = (u < 42);
    const int lane = t & 31;
    const unsigned pmask = 3u << (lane & ~1);   // shuffle pair mask

    const unsigned sbA = (unsigned)__cvta_generic_to_shared(
                             &im2t[(2 * h + i) * TC + s * BS]);
    const unsigned sbB = sbA + TC * 4u;   // next row
    const unsigned ib  = (unsigned)__cvta_generic_to_shared(
                             &im1t[2 * h * 16 + s * BS]);

    float vol[SS];
    float lmin = 1e30f;

    // ---- Phase 1: 2-row SADs with sliding-window loads, pair-reduce, local min
    if (act) {
        float a0, a1, a2, a3, b0, b1, b2, b3;
        asm("ld.shared.v4.f32 {%0,%1,%2,%3}, [%4];"
            : "=f"(a0), "=f"(a1), "=f"(a2), "=f"(a3) : "r"(ib));
        asm("ld.shared.v4.f32 {%0,%1,%2,%3}, [%4];"
            : "=f"(b0), "=f"(b1), "=f"(b2), "=f"(b3) : "r"(ib + 64u));
        float rA[TILE], rB[TILE];
        #pragma unroll
        for (int g = 0; g < 6; g++) {
            asm("ld.shared.v4.f32 {%0,%1,%2,%3}, [%4];"
                : "=f"(rA[4*g]), "=f"(rA[4*g+1]), "=f"(rA[4*g+2]), "=f"(rA[4*g+3])
                : "r"(sbA + 16u * g));
            asm("ld.shared.v4.f32 {%0,%1,%2,%3}, [%4];"
                : "=f"(rB[4*g]), "=f"(rB[4*g+1]), "=f"(rB[4*g+2]), "=f"(rB[4*g+3])
                : "r"(sbB + 16u * g));
            if (g >= 1) {
                #pragma unroll
                for (int jj = 0; jj < 4; jj++) {
                    int j = 4 * (g - 1) + jj;
                    vol[j] = fabsf(a0 - rA[j])     + fabsf(a1 - rA[j + 1])
                           + fabsf(a2 - rA[j + 2]) + fabsf(a3 - rA[j + 3])
                           + fabsf(b0 - rB[j])     + fabsf(b1 - rB[j + 1])
                           + fabsf(b2 - rB[j + 2]) + fabsf(b3 - rB[j + 3]);
                }
            }
        }
        vol[20] = fabsf(a0 - rA[20]) + fabsf(a1 - rA[21])
                + fabsf(a2 - rA[22]) + fabsf(a3 - rA[23])
                + fabsf(b0 - rB[20]) + fabsf(b1 - rB[21])
                + fabsf(b2 - rB[22]) + fabsf(b3 - rB[23]);

        // single-step pair allreduce over h (pair lanes end identical)
        #pragma unroll
        for (int j = 0; j < SS; j++)
            vol[j] += __shfl_xor_sync(pmask, vol[j], 1);

        // lane-local min — no CTA-wide reduction needed
        lmin = vol[0];
        #pragma unroll
        for (int j = 1; j < SS; j++) lmin = fminf(lmin, vol[j]);
        if (h == 0) smsg[s][i][0] = lmin;    // for phase-4 rescale
    }

    // ---- Phase 3: fused weights (local offset) + 2-row accumulation ----
    if (act) {
        // w = 2^(K*vol + M), K = -6.25*log2(e), M = -K*lmin (lane-local)
        const float K = -9.016844005555897f;
        const float M = -K * lmin;
        float lsum = 0.0f;
        float c0 = 0.f, c1 = 0.f, c2 = 0.f, c3 = 0.f;   // pixel row 2h
        float d0 = 0.f, d1 = 0.f, d2 = 0.f, d3 = 0.f;   // pixel row 2h+1
        float rA[TILE], rB[TILE];
        #pragma unroll
        for (int g = 0; g < 6; g++) {
            asm volatile("ld.shared.v4.f32 {%0,%1,%2,%3}, [%4];"
                : "=f"(rA[4*g]), "=f"(rA[4*g+1]), "=f"(rA[4*g+2]), "=f"(rA[4*g+3])
                : "r"(sbA + 16u * g));
            asm volatile("ld.shared.v4.f32 {%0,%1,%2,%3}, [%4];"
                : "=f"(rB[4*g]), "=f"(rB[4*g+1]), "=f"(rB[4*g+2]), "=f"(rB[4*g+3])
                : "r"(sbB + 16u * g));
            if (g >= 1) {
                #pragma unroll
                for (int jj = 0; jj < 4; jj++) {
                    int j = 4 * (g - 1) + jj;
                    float e = fmaf(vol[j], K, M);
                    float wv;
                    asm("ex2.approx.ftz.f32 %0, %1;" : "=f"(wv) : "f"(e));
                    lsum += wv;
                    c0 = fmaf(wv, rA[j],     c0);
                    c1 = fmaf(wv, rA[j + 1], c1);
                    c2 = fmaf(wv, rA[j + 2], c2);
                    c3 = fmaf(wv, rA[j + 3], c3);
                    d0 = fmaf(wv, rB[j],     d0);
                    d1 = fmaf(wv, rB[j + 1], d1);
                    d2 = fmaf(wv, rB[j + 2], d2);
                    d3 = fmaf(wv, rB[j + 3], d3);
                }
            }
        }
        {
            float e = fmaf(vol[20], K, M);
            float wv;
            asm("ex2.approx.ftz.f32 %0, %1;" : "=f"(wv) : "f"(e));
            lsum += wv;
            c0 = fmaf(wv, rA[20], c0); c1 = fmaf(wv, rA[21], c1);
            c2 = fmaf(wv, rA[22], c2); c3 = fmaf(wv, rA[23], c3);
            d0 = fmaf(wv, rB[20], d0); d1 = fmaf(wv, rB[21], d1);
            d2 = fmaf(wv, rB[22], d2); d3 = fmaf(wv, rB[23], d3);
        }
        if (h == 0) smsg[s][i][1] = lsum;    // pair lanes hold identical lsum
        *(float4*)&red[s][i][8 * h]     = make_float4(c0, c1, c2, c3);
        *(float4*)&red[s][i][8 * h + 4] = make_float4(d0, d1, d2, d3);
    }
    __syncthreads();

    // ---- Phase 4: split rescale-merge over 21 shift-rows (128 threads) ----
    // warp so handles sub-block so; half-warps split the q range (0..10 / 11..20).
    if (t < 128) {
        const int so   = t >> 5;
        const int half = (t >> 4) & 1;
        const int tt   = t & 15;
        const float K  = -9.016844005555897f;

        float mh;
        if (half == 0) {
            mh = smsg[so][0][0];
            #pragma unroll
            for (int q = 1; q < 11; q++) mh = fminf(mh, smsg[so][q][0]);
        } else {
            mh = smsg[so][11][0];
            #pragma unroll
            for (int q = 12; q < 21; q++) mh = fminf(mh, smsg[so][q][0]);
        }
        float mstar = fminf(mh, __shfl_xor_sync(0xffffffffu, mh, 16));

        float sum = 0.0f, ws = 0.0f;
        if (half == 0) {
            #pragma unroll
            for (int q = 0; q < 11; q++) {
                float2 msv = *(const float2*)&smsg[so][q][0];
                float e = K * (msv.x - mstar);
                float sc;
                asm("ex2.approx.ftz.f32 %0, %1;" : "=f"(sc) : "f"(e));
                sum = fmaf(sc, red[so][q][tt], sum);
                ws  = fmaf(sc, msv.y,          ws);
            }
        } else {
            #pragma unroll
            for (int q = 11; q < 21; q++) {
                float2 msv = *(const float2*)&smsg[so][q][0];
                float e = K * (msv.x - mstar);
                float sc;
                asm("ex2.approx.ftz.f32 %0, %1;" : "=f"(sc) : "f"(e));
                sum = fmaf(sc, red[so][q][tt], sum);
                ws  = fmaf(sc, msv.y,          ws);
            }
        }
        sum += __shfl_xor_sync(0xffffffffu, sum, 16);
        ws  += __shfl_xor_sync(0xffffffffu, ws, 16);

        if (half == 0) {
            int py2 = tt >> 2, px2 = tt & 3;
            out[b * H * W + (by * BS + py2) * W + bx * (NB * BS) + so * BS + px2]
                = __fdividef(sum, ws);
        }
    }
}

extern "C" void kernel_launch(void* const* d_in, const int* in_sizes, int n_in,
                              void* d_out, int out_size) {
    const float* im1 = (const float*)d_in[0];
    const float* im2 = (const float*)d_in[1];
    float* out = (float*)d_out;
    dim3 grid(W / (NB * BS), H / BS, 2);   // (16, 64, 2)
    pred_kernel<<<grid, NT>>>(im1, im2, out);
}